// round 15
// baseline (speedup 1.0000x reference)
#include <cuda_runtime.h>
#include <cstdint>

// ---------------- problem constants ----------------
#define SEQ   4096
#define BATCH 8
#define DIM   1024
#define ROWS  (SEQ*BATCH)        // 32768
#define N1    (3*DIM)            // 3072
#define NPAIR 4096               // b*h
#define NCH   128
#define CHL   32

// ---------------- GEMM tile config -----------------
#define BM 128
#define BN 256
#define BK 32
#define NK (DIM/BK)                       // 32 k-tiles
#define A_BYTES (BM*BK*4)                 // 16384
#define B_BYTES (BN*BK*4)                 // 32768
#define STAGE_BYTES (A_BYTES + B_BYTES)   // 49152
#define NSTAGE 4
#define SMEM_T (NSTAGE*STAGE_BYTES)       // 196608

// ---------------- scratch globals ------------------
__device__ float  g_V[ROWS*DIM];
__device__ float  g_Q[ROWS*DIM];
__device__ float  g_lam[ROWS*DIM];
__device__ float  g_o[ROWS*DIM];
__device__ float  g_xr[ROWS*DIM];
__device__ float  g_WinT[N1*DIM];    // W_in^T  [3072][1024], tf32-rounded
__device__ float  g_WoutT[DIM*DIM];  // W_out^T [1024][1024], tf32-rounded
__device__ float2 g_cA[NCH*NPAIR];
__device__ float4 g_cB[NCH*NPAIR];
__device__ float4 g_cS[NCH*NPAIR];

// ---------------- helpers --------------------------
__device__ __forceinline__ uint32_t smem_u32(const void* p) {
    uint32_t a;
    asm("{ .reg .u64 t; cvta.to.shared.u64 t, %1; cvt.u32.u64 %0, t; }"
        : "=r"(a) : "l"(p));
    return a;
}
__device__ __forceinline__ float rna_tf32(float f) {
    uint32_t u; asm("cvt.rna.tf32.f32 %0, %1;" : "=r"(u) : "f"(f));
    return __uint_as_float(u);
}
__device__ __forceinline__ float geluf(float x) {
    return 0.5f * x * (1.0f + erff(x * 0.70710678118654752f));
}
__device__ __forceinline__ float sigmf(float x) {
    return 1.0f / (1.0f + expf(-x));
}
__device__ __forceinline__ void cp16(uint32_t s, const void* g) {
    asm volatile("cp.async.cg.shared.global [%0], [%1], 16;" :: "r"(s), "l"(g));
}
__device__ __forceinline__ void cp_commit() {
    asm volatile("cp.async.commit_group;" ::: "memory");
}
template<int N> __device__ __forceinline__ void cp_wait() {
    asm volatile("cp.async.wait_group %0;" :: "n"(N) : "memory");
}
__device__ __forceinline__ void ldsm4(uint32_t* r, uint32_t addr) {
    asm volatile("ldmatrix.sync.aligned.m8n8.x4.shared.b16 {%0,%1,%2,%3}, [%4];"
        : "=r"(r[0]), "=r"(r[1]), "=r"(r[2]), "=r"(r[3]) : "r"(addr));
}
__device__ __forceinline__ void mma8(float* c, const uint32_t* a, const uint32_t* b) {
    asm volatile(
        "mma.sync.aligned.m16n8k8.row.col.f32.tf32.tf32.f32 "
        "{%0,%1,%2,%3}, {%4,%5,%6,%7}, {%8,%9}, {%0,%1,%2,%3};"
        : "+f"(c[0]), "+f"(c[1]), "+f"(c[2]), "+f"(c[3])
        : "r"(a[0]), "r"(a[1]), "r"(a[2]), "r"(a[3]), "r"(b[0]), "r"(b[1]));
}

// ---------------------------------------------------------------------------
// TF32 GEMM: ldmatrix + mma.sync, cp.async 4-stage smem pipeline, and a
// register-level fragment double-buffer: each k8-step issues the NEXT step's
// 8 LDSM.x4 before the current step's 32 MMAs, so LDSM latency is hidden by
// the MMA stream (ILP) instead of extra warps (TLP). 8 warps, warp tile 64x64.
// End-of-iter cp_wait<1>+syncthreads makes stage kt+2 visible before the
// cross-tile fragment prefetch that reads it.
// Smem rows 128B with XOR swizzle: off = row*128 + ((chunk*16) ^ ((row&7)<<4))
// MODE 0: A=g_xr, B=g_WinT, fused activation epilogue -> g_V/g_Q/g_lam
// MODE 1: A=g_o,  B=g_WoutT, plain store -> C
// ---------------------------------------------------------------------------
template<int MODE>
__global__ __launch_bounds__(256, 1)
void gemm_tc(const float* __restrict__ lb, float* __restrict__ C)
{
    extern __shared__ char smem[];
    const uint32_t sb = smem_u32(smem);
    const int tid = threadIdx.x, lane = tid & 31, warp = tid >> 5;
    const int wm = (warp & 1) * 64;   // 2 warps along M (64 rows each)
    const int wn = (warp >> 1) * 64;  // 4 warps along N (64 cols each)
    const int bM = blockIdx.y, bN = blockIdx.x;

    const float* A = (MODE == 0) ? g_xr   : g_o;
    const float* B = (MODE == 0) ? g_WinT : g_WoutT;

    // ---- global->smem mapping ----
    const int arow = tid >> 1;
    const int ac0  = (tid & 1) * 4;
    const float* gA = A + (size_t)(bM * BM + arow) * DIM + ac0 * 4;
    const uint32_t aX = ((uint32_t)(arow & 7)) << 4;
    const float* gB = B + (size_t)(bN * BN + tid) * DIM;
    const uint32_t bX = ((uint32_t)(tid & 7)) << 4;

    auto load_stage = [&](int s, int kt) {
        uint32_t st = sb + s * STAGE_BYTES;
        const float* ga = gA + kt * BK;
        const float* gb = gB + kt * BK;
        uint32_t sa = st + arow * 128;
        #pragma unroll
        for (int i = 0; i < 4; i++)
            cp16(sa + ((((ac0 + i) * 16) ^ aX)), ga + i * 4);
        uint32_t sbB = st + A_BYTES + tid * 128;
        #pragma unroll
        for (int i = 0; i < 8; i++)
            cp16(sbB + ((i * 16) ^ bX), gb + i * 4);
        cp_commit();
    };

    // ---- ldmatrix addressing ----
    const int aRowL = lane & 15, aCh = lane >> 4;
    const int bRowL = (lane & 7) + ((lane >> 4) << 3), bCh = (lane >> 3) & 1;
    uint32_t aBase[4], aSx[4], bBase[4], bSx[4];
    #pragma unroll
    for (int tm = 0; tm < 4; tm++) {
        int r = wm + tm * 16 + aRowL;
        aBase[tm] = r * 128;
        aSx[tm]   = (aCh * 16) ^ ((r & 7) << 4);
    }
    #pragma unroll
    for (int p = 0; p < 4; p++) {
        int r = wn + p * 16 + bRowL;
        bBase[p] = r * 128;
        bSx[p]   = (bCh * 16) ^ ((r & 7) << 4);
    }

    // fragment double buffers
    uint32_t af[2][4][4], bf[2][4][4];
    auto preload = [&](uint32_t stA, uint32_t kk4, int buf) {
        const uint32_t stB = stA + A_BYTES;
        #pragma unroll
        for (int tm = 0; tm < 4; tm++)
            ldsm4(af[buf][tm], stA + aBase[tm] + (kk4 ^ aSx[tm]));
        #pragma unroll
        for (int p = 0; p < 4; p++)
            ldsm4(bf[buf][p], stB + bBase[p] + (kk4 ^ bSx[p]));
    };

    float acc[4][8][4];
    #pragma unroll
    for (int i = 0; i < 4; i++)
        #pragma unroll
        for (int j = 0; j < 8; j++)
            #pragma unroll
            for (int k = 0; k < 4; k++) acc[i][j][k] = 0.f;

    // ---- pipeline ----
    load_stage(0, 0);
    load_stage(1, 1);
    load_stage(2, 2);
    cp_wait<2>();          // stages 0,1 complete
    __syncthreads();       // ... and visible SM-wide
    preload(sb, 0, 0);     // fragments for kt=0, kk=0

    int cur = 0;
    #pragma unroll 1
    for (int kt = 0; kt < NK; kt++) {
        if (kt + 3 < NK) load_stage((kt + 3) & 3, kt + 3);
        else             cp_commit();         // keep group counting aligned

        const uint32_t stc = sb + (kt & 3) * STAGE_BYTES;
        const uint32_t stn = sb + ((kt + 1) & 3) * STAGE_BYTES;

        #pragma unroll
        for (int kk = 0; kk < 4; kk++) {
            const int nb = cur ^ 1;
            // prefetch next k8-step's fragments (cross-tile at kk==3)
            if (kk < 3)            preload(stc, (uint32_t)(kk + 1) * 32, nb);
            else if (kt + 1 < NK)  preload(stn, 0, nb);
            // MMAs on the resident buffer
            #pragma unroll
            for (int tm = 0; tm < 4; tm++) {
                #pragma unroll
                for (int p = 0; p < 4; p++) {
                    mma8(acc[tm][2 * p],     af[cur][tm], &bf[cur][p][0]);
                    mma8(acc[tm][2 * p + 1], af[cur][tm], &bf[cur][p][2]);
                }
            }
            cur = nb;
        }

        cp_wait<1>();      // stages <= kt+2 complete (next iter reads kt+2)
        __syncthreads();   // visible to all; frees stage (kt+4)&3 for reuse
    }

    // ---------------- epilogue ----------------
    const int gq = lane >> 2, tg = lane & 3;
    const int seg = (MODE == 0) ? ((bN * BN) >> 10) : 0;  // 0:V 1:Q 2:gate
    #pragma unroll
    for (int tm = 0; tm < 4; tm++) {
        #pragma unroll
        for (int tn = 0; tn < 8; tn++) {
            float* c = acc[tm][tn];
            int m = bM * BM + wm + tm * 16 + gq;
            int n = bN * BN + wn + tn * 8 + 2 * tg;
            if (MODE == 1) {
                *(float2*)&C[(size_t)m * DIM + n]       = make_float2(c[0], c[1]);
                *(float2*)&C[(size_t)(m + 8) * DIM + n] = make_float2(c[2], c[3]);
            } else {
                int cis = n & 1023;
                if (seg == 0) {
                    *(float2*)&g_V[(size_t)m * DIM + cis] =
                        make_float2(geluf(c[0]), geluf(c[1]));
                    *(float2*)&g_V[(size_t)(m + 8) * DIM + cis] =
                        make_float2(geluf(c[2]), geluf(c[3]));
                } else if (seg == 1) {
                    *(float2*)&g_Q[(size_t)m * DIM + cis] =
                        make_float2(geluf(c[0]), geluf(c[1]));
                    *(float2*)&g_Q[(size_t)(m + 8) * DIM + cis] =
                        make_float2(geluf(c[2]), geluf(c[3]));
                } else {
                    float b0 = lb[cis], b1 = lb[cis + 1];
                    *(float2*)&g_lam[(size_t)m * DIM + cis] = make_float2(
                        b0 + (1.f - b0) * sigmf(c[0]),
                        b1 + (1.f - b1) * sigmf(c[1]));
                    *(float2*)&g_lam[(size_t)(m + 8) * DIM + cis] = make_float2(
                        b0 + (1.f - b0) * sigmf(c[2]),
                        b1 + (1.f - b1) * sigmf(c[3]));
                }
            }
        }
    }
}

// ---------------------------------------------------------------------------
// prep kernels: tf32-round x; transpose+round weights to K-major
// ---------------------------------------------------------------------------
__global__ __launch_bounds__(256) void round_x_k(const float4* __restrict__ x) {
    int i = blockIdx.x * 256 + threadIdx.x;
    float4 v = x[i];
    ((float4*)g_xr)[i] = make_float4(rna_tf32(v.x), rna_tf32(v.y),
                                     rna_tf32(v.z), rna_tf32(v.w));
}

template<int W>  // 0: W_in -> g_WinT (C=3072), 1: W_out -> g_WoutT (C=1024)
__global__ __launch_bounds__(256) void transposeW(const float* __restrict__ in, int C) {
    __shared__ float t[32][33];
    float* out = W ? g_WoutT : g_WinT;
    int bx = blockIdx.x * 32, by = blockIdx.y * 32;
    int tx = threadIdx.x, ty = threadIdx.y;       // block (32,8)
    #pragma unroll
    for (int j = 0; j < 32; j += 8)
        t[ty + j][tx] = in[(size_t)(by + ty + j) * C + bx + tx];
    __syncthreads();
    #pragma unroll
    for (int j = 0; j < 32; j += 8)
        out[(size_t)(bx + ty + j) * DIM + by + tx] = rna_tf32(t[tx][ty + j]);
}

// ---------------------------------------------------------------------------
// GLA chunked scan (pass3 rounds o to tf32 for GEMM2)
// ---------------------------------------------------------------------------
__global__ __launch_bounds__(256) void scan_pass1() {
    int g = blockIdx.x * 256 + threadIdx.x;
    int pair = g & (NPAIR - 1);
    int c = g >> 12;
    const float2* lam2 = (const float2*)g_lam;
    const float2* V2 = (const float2*)g_V;
    int base = c * CHL * NPAIR + pair;
    float S00 = 0.f, S01 = 0.f, S10 = 0.f, S11 = 0.f, A0 = 1.f, A1 = 1.f;
    #pragma unroll 8
    for (int i = 0; i < CHL; i++) {
        float2 lm = lam2[base + i * NPAIR];
        float2 v = V2[base + i * NPAIR];
        float k0 = 1.f - lm.x, k1 = 1.f - lm.y;
        S00 = fmaf(lm.x, S00, k0 * v.x);
        S01 = fmaf(lm.x, S01, k0 * v.y);
        S10 = fmaf(lm.y, S10, k1 * v.x);
        S11 = fmaf(lm.y, S11, k1 * v.y);
        A0 *= lm.x; A1 *= lm.y;
    }
    g_cA[g] = make_float2(A0, A1);
    g_cB[g] = make_float4(S00, S01, S10, S11);
}

__global__ __launch_bounds__(256) void scan_pass2() {
    int pair = blockIdx.x * 256 + threadIdx.x;
    float S00 = 0.f, S01 = 0.f, S10 = 0.f, S11 = 0.f;
    #pragma unroll 4
    for (int c = 0; c < NCH; c++) {
        int idx = c * NPAIR + pair;
        g_cS[idx] = make_float4(S00, S01, S10, S11);
        float2 a = g_cA[idx];
        float4 b = g_cB[idx];
        S00 = fmaf(a.x, S00, b.x);
        S01 = fmaf(a.x, S01, b.y);
        S10 = fmaf(a.y, S10, b.z);
        S11 = fmaf(a.y, S11, b.w);
    }
}

__global__ __launch_bounds__(256) void scan_pass3() {
    int g = blockIdx.x * 256 + threadIdx.x;
    int pair = g & (NPAIR - 1);
    int c = g >> 12;
    const float2* lam2 = (const float2*)g_lam;
    const float2* V2 = (const float2*)g_V;
    const float2* Q2 = (const float2*)g_Q;
    float2* O2 = (float2*)g_o;
    int base = c * CHL * NPAIR + pair;
    float4 s = g_cS[g];
    float S00 = s.x, S01 = s.y, S10 = s.z, S11 = s.w;
    #pragma unroll 4
    for (int i = 0; i < CHL; i++) {
        float2 lm = lam2[base + i * NPAIR];
        float2 v = V2[base + i * NPAIR];
        float2 q = Q2[base + i * NPAIR];
        float k0 = 1.f - lm.x, k1 = 1.f - lm.y;
        S00 = fmaf(lm.x, S00, k0 * v.x);
        S01 = fmaf(lm.x, S01, k0 * v.y);
        S10 = fmaf(lm.y, S10, k1 * v.x);
        S11 = fmaf(lm.y, S11, k1 * v.y);
        float2 o;
        o.x = rna_tf32(fmaf(q.x, S00, q.y * S10));
        o.y = rna_tf32(fmaf(q.x, S01, q.y * S11));
        O2[base + i * NPAIR] = o;
    }
}

// ---------------------------------------------------------------------------
extern "C" void kernel_launch(void* const* d_in, const int* in_sizes, int n_in,
                              void* d_out, int out_size)
{
    const float* x     = (const float*)d_in[0];
    const float* lb    = (const float*)d_in[1];
    const float* W_in  = (const float*)d_in[2];
    const float* W_out = (const float*)d_in[3];
    float* out = (float*)d_out;

    cudaFuncSetAttribute(gemm_tc<0>, cudaFuncAttributeMaxDynamicSharedMemorySize, SMEM_T);
    cudaFuncSetAttribute(gemm_tc<1>, cudaFuncAttributeMaxDynamicSharedMemorySize, SMEM_T);

    // prep: round x to tf32; transpose+round weights to K-major
    round_x_k<<<(ROWS * DIM) / 1024, 256>>>((const float4*)x);
    transposeW<0><<<dim3(N1 / 32, DIM / 32), dim3(32, 8)>>>(W_in, N1);
    transposeW<1><<<dim3(DIM / 32, DIM / 32), dim3(32, 8)>>>(W_out, DIM);

    // feat = x @ W_in (+gelu/gelu/gate) -> g_V, g_Q, g_lam
    gemm_tc<0><<<dim3(N1 / BN, ROWS / BM), 256, SMEM_T>>>(lb, nullptr);

    // chunked GLA scan -> g_o (tf32-rounded)
    scan_pass1<<<(NCH * NPAIR) / 256, 256>>>();
    scan_pass2<<<NPAIR / 256, 256>>>();
    scan_pass3<<<(NCH * NPAIR) / 256, 256>>>();

    // out = o @ W_out
    gemm_tc<1><<<dim3(DIM / BN, ROWS / BM), 256, SMEM_T>>>(nullptr, out);
}

// round 17
// speedup vs baseline: 3.2526x; 3.2526x over previous
#include <cuda_runtime.h>
#include <cuda_fp16.h>
#include <cstdint>

// ---------------- problem constants ----------------
#define SEQ   4096
#define BATCH 8
#define DIM   1024
#define ROWS  (SEQ*BATCH)        // 32768
#define N1    (3*DIM)            // 3072
#define NPAIR 4096               // b*h
#define NCH   128
#define CHL   32

// ---------------- GEMM tile config -----------------
#define BM 128
#define BN 128
#define BK 64                              // 64 fp16 = 128B row
#define NK (DIM/BK)                        // 16 k-tiles
#define A_BYTES (BM*BK*2)                  // 16384
#define B_BYTES (BN*BK*2)                  // 16384
#define STAGE_BYTES (A_BYTES + B_BYTES)    // 32768
#define NSTAGE 3
#define SMEM_T (NSTAGE*STAGE_BYTES)        // 98304 -> 2 CTAs/SM

// ---------------- scratch globals ------------------
__device__ float  g_V[ROWS*DIM];
__device__ float  g_Q[ROWS*DIM];
__device__ float  g_lam[ROWS*DIM];
__device__ __half g_xh[ROWS*DIM];     // x, fp16
__device__ __half g_oh[ROWS*DIM];     // scan output, fp16 (GEMM2 operand)
__device__ __half g_WinTh[N1*DIM];    // W_in^T  [3072][1024] fp16
__device__ __half g_WoutTh[DIM*DIM];  // W_out^T [1024][1024] fp16
__device__ float2 g_cA[NCH*NPAIR];
__device__ float4 g_cB[NCH*NPAIR];
__device__ float4 g_cS[NCH*NPAIR];

// ---------------- helpers --------------------------
__device__ __forceinline__ uint32_t smem_u32(const void* p) {
    uint32_t a;
    asm("{ .reg .u64 t; cvta.to.shared.u64 t, %1; cvt.u32.u64 %0, t; }"
        : "=r"(a) : "l"(p));
    return a;
}
__device__ __forceinline__ float geluf(float x) {
    return 0.5f * x * (1.0f + erff(x * 0.70710678118654752f));
}
__device__ __forceinline__ float sigmf(float x) {
    return 1.0f / (1.0f + expf(-x));
}
__device__ __forceinline__ void cp16(uint32_t s, const void* g) {
    asm volatile("cp.async.cg.shared.global [%0], [%1], 16;" :: "r"(s), "l"(g));
}
__device__ __forceinline__ void cp_commit() {
    asm volatile("cp.async.commit_group;" ::: "memory");
}
template<int N> __device__ __forceinline__ void cp_wait() {
    asm volatile("cp.async.wait_group %0;" :: "n"(N) : "memory");
}
__device__ __forceinline__ void ldsm4(uint32_t* r, uint32_t addr) {
    asm volatile("ldmatrix.sync.aligned.m8n8.x4.shared.b16 {%0,%1,%2,%3}, [%4];"
        : "=r"(r[0]), "=r"(r[1]), "=r"(r[2]), "=r"(r[3]) : "r"(addr));
}
// m16n8k16 fp16 HMMA, fp32 accumulate
__device__ __forceinline__ void mma16(float* c, const uint32_t* a, const uint32_t* b) {
    asm volatile(
        "mma.sync.aligned.m16n8k16.row.col.f32.f16.f16.f32 "
        "{%0,%1,%2,%3}, {%4,%5,%6,%7}, {%8,%9}, {%0,%1,%2,%3};"
        : "+f"(c[0]), "+f"(c[1]), "+f"(c[2]), "+f"(c[3])
        : "r"(a[0]), "r"(a[1]), "r"(a[2]), "r"(a[3]), "r"(b[0]), "r"(b[1]));
}

// ---------------------------------------------------------------------------
// FP16 GEMM (fp32 accum): C[M, Ntot] = A[M,1024] @ Bt^T, Bt [Ntot,1024] K-major.
// fp16 mantissa == tf32 mantissa (10 bits) -> same error as previous tf32 path,
// at half the smem traffic and double MACs/HMMA slot (m16n8k16).
// 8 warps, warp tile 64x32 (R9's proven occupancy structure), 2 CTAs/SM.
// Smem rows 128B (= BK=64 fp16) with XOR swizzle:
//   off(row,chunk16B) = row*128 + ((chunk*16) ^ ((row&7)<<4))
// MODE 0: A=g_xh, B=g_WinTh, fused activation epilogue -> g_V/g_Q/g_lam (fp32)
// MODE 1: A=g_oh, B=g_WoutTh, plain fp32 store -> C
// ---------------------------------------------------------------------------
template<int MODE>
__global__ __launch_bounds__(256, 2)
void gemm_tc(const float* __restrict__ lb, float* __restrict__ C)
{
    extern __shared__ char smem[];
    const uint32_t sb = smem_u32(smem);
    const int tid = threadIdx.x, lane = tid & 31, warp = tid >> 5;
    const int wm = (warp & 1) * 64;   // 2 warps along M
    const int wn = (warp >> 1) * 32;  // 4 warps along N
    const int bM = blockIdx.y, bN = blockIdx.x;

    const __half* A = (MODE == 0) ? g_xh    : g_oh;
    const __half* B = (MODE == 0) ? g_WinTh : g_WoutTh;

    // ---- global->smem: thread t -> row tid>>1, 4 chunks of 16B (8 fp16) ----
    const int grow = tid >> 1;
    const int gc0  = (tid & 1) * 4;          // chunk index 0..7
    const __half* gA = A + (size_t)(bM * BM + grow) * DIM + gc0 * 8;
    const __half* gB = B + (size_t)(bN * BN + grow) * DIM + gc0 * 8;
    const uint32_t gX = ((uint32_t)(grow & 7)) << 4;
    uint32_t sOff[4];
    #pragma unroll
    for (int i = 0; i < 4; i++)
        sOff[i] = grow * 128 + (((gc0 + i) * 16) ^ gX);

    auto load_stage = [&](int s, int kt) {
        uint32_t st = sb + s * STAGE_BYTES;
        const __half* ga = gA + kt * BK;
        const __half* gb = gB + kt * BK;
        #pragma unroll
        for (int i = 0; i < 4; i++) cp16(st + sOff[i], ga + i * 8);
        #pragma unroll
        for (int i = 0; i < 4; i++) cp16(st + A_BYTES + sOff[i], gb + i * 8);
        cp_commit();
    };

    // ---- ldmatrix addressing ----
    // A x4 (16x16 tile): lanes0-15 -> rows, lane>>4 -> k-chunk (16B)
    const int aRowL = lane & 15, aCh = lane >> 4;
    // B x4 (two n8 tiles x k16): rows = (lane&7)+((lane>>4)<<3), chunk = (lane>>3)&1
    const int bRowL = (lane & 7) + ((lane >> 4) << 3), bCh = (lane >> 3) & 1;
    uint32_t aBase[4], aSx[4], bBase[2], bSx[2];
    #pragma unroll
    for (int tm = 0; tm < 4; tm++) {
        int r = wm + tm * 16 + aRowL;
        aBase[tm] = r * 128;
        aSx[tm]   = (aCh * 16) ^ ((r & 7) << 4);
    }
    #pragma unroll
    for (int p = 0; p < 2; p++) {
        int r = wn + p * 16 + bRowL;
        bBase[p] = r * 128;
        bSx[p]   = (bCh * 16) ^ ((r & 7) << 4);
    }

    float acc[4][4][4];
    #pragma unroll
    for (int i = 0; i < 4; i++)
        #pragma unroll
        for (int j = 0; j < 4; j++)
            #pragma unroll
            for (int k = 0; k < 4; k++) acc[i][j][k] = 0.f;

    // ---- pipeline (R9 structure) ----
    load_stage(0, 0);
    load_stage(1, 1);

    #pragma unroll 1
    for (int kt = 0; kt < NK; kt++) {
        cp_wait<1>();
        __syncthreads();                      // stage kt%3 visible; frees (kt+2)%3
        if (kt + 2 < NK) load_stage((kt + 2) % NSTAGE, kt + 2);
        else             cp_commit();         // keep group counting aligned

        const uint32_t sA = sb + (kt % NSTAGE) * STAGE_BYTES;
        const uint32_t sB = sA + A_BYTES;

        #pragma unroll
        for (int kk = 0; kk < 4; kk++) {      // 4 k16-steps per BK=64
            const uint32_t ko = (uint32_t)kk * 32;   // 32B per k16
            uint32_t af[4][4], bf[2][4];
            #pragma unroll
            for (int tm = 0; tm < 4; tm++)
                ldsm4(af[tm], sA + aBase[tm] + (ko ^ aSx[tm]));
            #pragma unroll
            for (int p = 0; p < 2; p++)
                ldsm4(bf[p], sB + bBase[p] + (ko ^ bSx[p]));
            // bf[p] = {n(p*16..+7)k0-7, same k8-15, n(+8..+15)k0-7, same k8-15}
            #pragma unroll
            for (int tm = 0; tm < 4; tm++) {
                mma16(acc[tm][0], af[tm], &bf[0][0]);
                mma16(acc[tm][1], af[tm], &bf[0][2]);
                mma16(acc[tm][2], af[tm], &bf[1][0]);
                mma16(acc[tm][3], af[tm], &bf[1][2]);
            }
        }
    }

    // ---------------- epilogue ----------------
    const int gq = lane >> 2, tg = lane & 3;
    const int seg = (MODE == 0) ? ((bN * BN) >> 10) : 0;  // 0:V 1:Q 2:gate
    #pragma unroll
    for (int tm = 0; tm < 4; tm++) {
        #pragma unroll
        for (int tn = 0; tn < 4; tn++) {
            float* c = acc[tm][tn];
            int m = bM * BM + wm + tm * 16 + gq;
            int n = bN * BN + wn + tn * 8 + 2 * tg;
            if (MODE == 1) {
                *(float2*)&C[(size_t)m * DIM + n]       = make_float2(c[0], c[1]);
                *(float2*)&C[(size_t)(m + 8) * DIM + n] = make_float2(c[2], c[3]);
            } else {
                int cis = n & 1023;
                if (seg == 0) {
                    *(float2*)&g_V[(size_t)m * DIM + cis] =
                        make_float2(geluf(c[0]), geluf(c[1]));
                    *(float2*)&g_V[(size_t)(m + 8) * DIM + cis] =
                        make_float2(geluf(c[2]), geluf(c[3]));
                } else if (seg == 1) {
                    *(float2*)&g_Q[(size_t)m * DIM + cis] =
                        make_float2(geluf(c[0]), geluf(c[1]));
                    *(float2*)&g_Q[(size_t)(m + 8) * DIM + cis] =
                        make_float2(geluf(c[2]), geluf(c[3]));
                } else {
                    float b0 = lb[cis], b1 = lb[cis + 1];
                    *(float2*)&g_lam[(size_t)m * DIM + cis] = make_float2(
                        b0 + (1.f - b0) * sigmf(c[0]),
                        b1 + (1.f - b1) * sigmf(c[1]));
                    *(float2*)&g_lam[(size_t)(m + 8) * DIM + cis] = make_float2(
                        b0 + (1.f - b0) * sigmf(c[2]),
                        b1 + (1.f - b1) * sigmf(c[3]));
                }
            }
        }
    }
}

// ---------------------------------------------------------------------------
// prep kernels: x -> fp16; transpose weights to K-major fp16
// ---------------------------------------------------------------------------
__global__ __launch_bounds__(256) void round_x_k(const float4* __restrict__ x) {
    int i = blockIdx.x * 256 + threadIdx.x;
    float4 v = x[i];
    __half2* o = (__half2*)g_xh;
    o[2 * i]     = __floats2half2_rn(v.x, v.y);
    o[2 * i + 1] = __floats2half2_rn(v.z, v.w);
}

template<int W>  // 0: W_in -> g_WinTh (C=3072), 1: W_out -> g_WoutTh (C=1024)
__global__ __launch_bounds__(256) void transposeW(const float* __restrict__ in, int C) {
    __shared__ float t[32][33];
    __half* out = W ? g_WoutTh : g_WinTh;
    int bx = blockIdx.x * 32, by = blockIdx.y * 32;
    int tx = threadIdx.x, ty = threadIdx.y;       // block (32,8)
    #pragma unroll
    for (int j = 0; j < 32; j += 8)
        t[ty + j][tx] = in[(size_t)(by + ty + j) * C + bx + tx];
    __syncthreads();
    #pragma unroll
    for (int j = 0; j < 32; j += 8)
        out[(size_t)(bx + ty + j) * DIM + by + tx] = __float2half_rn(t[tx][ty + j]);
}

// ---------------------------------------------------------------------------
// GLA chunked scan — fp32 end-to-end (lambda precision is critical);
// pass3 emits fp16 o for GEMM2 (same mantissa as the old tf32 rounding).
// ---------------------------------------------------------------------------
__global__ __launch_bounds__(256) void scan_pass1() {
    int g = blockIdx.x * 256 + threadIdx.x;
    int pair = g & (NPAIR - 1);
    int c = g >> 12;
    const float2* lam2 = (const float2*)g_lam;
    const float2* V2 = (const float2*)g_V;
    int base = c * CHL * NPAIR + pair;
    float S00 = 0.f, S01 = 0.f, S10 = 0.f, S11 = 0.f, A0 = 1.f, A1 = 1.f;
    #pragma unroll 8
    for (int i = 0; i < CHL; i++) {
        float2 lm = lam2[base + i * NPAIR];
        float2 v = V2[base + i * NPAIR];
        float k0 = 1.f - lm.x, k1 = 1.f - lm.y;
        S00 = fmaf(lm.x, S00, k0 * v.x);
        S01 = fmaf(lm.x, S01, k0 * v.y);
        S10 = fmaf(lm.y, S10, k1 * v.x);
        S11 = fmaf(lm.y, S11, k1 * v.y);
        A0 *= lm.x; A1 *= lm.y;
    }
    g_cA[g] = make_float2(A0, A1);
    g_cB[g] = make_float4(S00, S01, S10, S11);
}

__global__ __launch_bounds__(256) void scan_pass2() {
    int pair = blockIdx.x * 256 + threadIdx.x;
    float S00 = 0.f, S01 = 0.f, S10 = 0.f, S11 = 0.f;
    #pragma unroll 4
    for (int c = 0; c < NCH; c++) {
        int idx = c * NPAIR + pair;
        g_cS[idx] = make_float4(S00, S01, S10, S11);
        float2 a = g_cA[idx];
        float4 b = g_cB[idx];
        S00 = fmaf(a.x, S00, b.x);
        S01 = fmaf(a.x, S01, b.y);
        S10 = fmaf(a.y, S10, b.z);
        S11 = fmaf(a.y, S11, b.w);
    }
}

__global__ __launch_bounds__(256) void scan_pass3() {
    int g = blockIdx.x * 256 + threadIdx.x;
    int pair = g & (NPAIR - 1);
    int c = g >> 12;
    const float2* lam2 = (const float2*)g_lam;
    const float2* V2 = (const float2*)g_V;
    const float2* Q2 = (const float2*)g_Q;
    __half2* O2 = (__half2*)g_oh;
    int base = c * CHL * NPAIR + pair;
    float4 s = g_cS[g];
    float S00 = s.x, S01 = s.y, S10 = s.z, S11 = s.w;
    #pragma unroll 4
    for (int i = 0; i < CHL; i++) {
        float2 lm = lam2[base + i * NPAIR];
        float2 v = V2[base + i * NPAIR];
        float2 q = Q2[base + i * NPAIR];
        float k0 = 1.f - lm.x, k1 = 1.f - lm.y;
        S00 = fmaf(lm.x, S00, k0 * v.x);
        S01 = fmaf(lm.x, S01, k0 * v.y);
        S10 = fmaf(lm.y, S10, k1 * v.x);
        S11 = fmaf(lm.y, S11, k1 * v.y);
        float ox = fmaf(q.x, S00, q.y * S10);
        float oy = fmaf(q.x, S01, q.y * S11);
        O2[base + i * NPAIR] = __floats2half2_rn(ox, oy);
    }
}

// ---------------------------------------------------------------------------
extern "C" void kernel_launch(void* const* d_in, const int* in_sizes, int n_in,
                              void* d_out, int out_size)
{
    const float* x     = (const float*)d_in[0];
    const float* lb    = (const float*)d_in[1];
    const float* W_in  = (const float*)d_in[2];
    const float* W_out = (const float*)d_in[3];
    float* out = (float*)d_out;

    cudaFuncSetAttribute(gemm_tc<0>, cudaFuncAttributeMaxDynamicSharedMemorySize, SMEM_T);
    cudaFuncSetAttribute(gemm_tc<1>, cudaFuncAttributeMaxDynamicSharedMemorySize, SMEM_T);

    // prep: x -> fp16; transpose weights to K-major fp16
    round_x_k<<<(ROWS * DIM) / 1024, 256>>>((const float4*)x);
    transposeW<0><<<dim3(N1 / 32, DIM / 32), dim3(32, 8)>>>(W_in, N1);
    transposeW<1><<<dim3(DIM / 32, DIM / 32), dim3(32, 8)>>>(W_out, DIM);

    // feat = x @ W_in (+gelu/gelu/gate) -> g_V, g_Q, g_lam (fp32)
    gemm_tc<0><<<dim3(N1 / BN, ROWS / BM), 256, SMEM_T>>>(lb, nullptr);

    // chunked GLA scan (fp32) -> g_oh (fp16)
    scan_pass1<<<(NCH * NPAIR) / 256, 256>>>();
    scan_pass2<<<NPAIR / 256, 256>>>();
    scan_pass3<<<(NCH * NPAIR) / 256, 256>>>();

    // out = o @ W_out
    gemm_tc<1><<<dim3(DIM / BN, ROWS / BM), 256, SMEM_T>>>(nullptr, out);
}